// round 4
// baseline (speedup 1.0000x reference)
#include <cuda_runtime.h>

#define N_NODES 50000
#define M_NB    16
#define NCAPS   8
#define NHID    16
#define DIM     128
#define ROUTIT  6

#define FULLMASK 0xffffffffu

// Scratch (no allocation allowed): static device buffers.
__device__ float g_xn[N_NODES * DIM];  // normalized layer-0 input
__device__ float g_h1[N_NODES * DIM];  // layer-0 routing output (relu'd)
__device__ float g_y [N_NODES * DIM];  // normalize(relu(fc(h1)))

// ---- f32x2 packed helpers (sm_103a) ---------------------------------------
__device__ __forceinline__ unsigned long long fma2(unsigned long long a,
                                                   unsigned long long b,
                                                   unsigned long long c)
{
    unsigned long long d;
    asm("fma.rn.f32x2 %0, %1, %2, %3;" : "=l"(d) : "l"(a), "l"(b), "l"(c));
    return d;
}
__device__ __forceinline__ unsigned long long mul2(unsigned long long a,
                                                   unsigned long long b)
{
    unsigned long long d;
    asm("mul.rn.f32x2 %0, %1, %2;" : "=l"(d) : "l"(a), "l"(b));
    return d;
}
__device__ __forceinline__ unsigned long long pack2(float lo, float hi)
{
    unsigned long long d;
    asm("mov.b64 %0, {%1, %2};" : "=l"(d) : "f"(lo), "f"(hi));
    return d;
}
__device__ __forceinline__ void unpack2(unsigned long long v, float& lo, float& hi)
{
    asm("mov.b64 {%0, %1}, %2;" : "=f"(lo), "=f"(hi) : "l"(v));
}

// ---------------------------------------------------------------------------
// K1: per-capsule L2 normalize of raw x -> g_xn
// ---------------------------------------------------------------------------
__global__ __launch_bounds__(256) void normalize_kernel(const float* __restrict__ x)
{
    int idx = blockIdx.x * blockDim.x + threadIdx.x;       // capsule index
    if (idx >= N_NODES * NCAPS) return;
    const float4* src = reinterpret_cast<const float4*>(x) + idx * 4;
    float4 v0 = src[0], v1 = src[1], v2 = src[2], v3 = src[3];
    float ss = v0.x*v0.x + v0.y*v0.y + v0.z*v0.z + v0.w*v0.w
             + v1.x*v1.x + v1.y*v1.y + v1.z*v1.z + v1.w*v1.w
             + v2.x*v2.x + v2.y*v2.y + v2.z*v2.z + v2.w*v2.w
             + v3.x*v3.x + v3.y*v3.y + v3.z*v3.z + v3.w*v3.w;
    float inv = rsqrtf(fmaxf(ss, 1e-24f));
    float4* dst = reinterpret_cast<float4*>(g_xn) + idx * 4;
    v0.x*=inv; v0.y*=inv; v0.z*=inv; v0.w*=inv;
    v1.x*=inv; v1.y*=inv; v1.z*=inv; v1.w*=inv;
    v2.x*=inv; v2.y*=inv; v2.z*=inv; v2.w*=inv;
    v3.x*=inv; v3.y*=inv; v3.z*=inv; v3.w*=inv;
    dst[0]=v0; dst[1]=v1; dst[2]=v2; dst[3]=v3;
}

// ---------------------------------------------------------------------------
// Warp-per-node routing. Lane L: capsule k = L>>2, dim-group dg = L&3
// (owns dims 4*dg..4*dg+3 of capsule k). All state in registers; no smem.
//
// Permuted gather: register slot s holds z of neighbor m = (s&~3)|((s&3)^dg).
// => butterfly reduce-scatter and p-allgather need NO runtime selects.
// After reduce-scatter, s[i] is the full dot for m = 4i + (dg^3).
// After allgather, pD/pB/pC/pA hold p for m-offset dg / dg^1 / dg^2 / dg^3,
// matching slots s&3 == 0 / 1 / 2 / 3 respectively (compile-time mapping).
// ---------------------------------------------------------------------------
__device__ __forceinline__ void routing_warp(const float* __restrict__ src,
                                             const int*   __restrict__ nb,
                                             float*       __restrict__ out)
{
    const int lane = threadIdx.x & 31;
    const int node = blockIdx.x * 8 + (threadIdx.x >> 5);
    const int dg   = lane & 3;

    // Broadcast neighbor indices: lanes 0..15 load one each.
    int nbv = 0;
    if (lane < 16) nbv = nb[node * M_NB + lane];

    const ulonglong2* srcv = reinterpret_cast<const ulonglong2*>(src);

    // xn / u init: this lane's 4 floats as two f32x2 pairs.
    ulonglong2 xn = srcv[node * 32 + lane];
    ulonglong2 u  = xn;

    // Gather z with dg-permuted slots (coalesced 16B per lane per row).
    ulonglong2 z[M_NB];
#pragma unroll
    for (int s = 0; s < M_NB; s++) {
        int row = __shfl_sync(FULLMASK, nbv, s ^ dg);
        z[s] = srcv[row * 32 + lane];
    }

    const unsigned long long ZERO = 0;
    ulonglong2 unew = xn;

#pragma unroll
    for (int it = 0; it < ROUTIT; it++) {
        // ---- phase A: partial dots (own 4 dims) for each slot ----
        float a[M_NB];
#pragma unroll
        for (int s = 0; s < M_NB; s++) {
            unsigned long long acc = fma2(z[s].x, u.x, fma2(z[s].y, u.y, ZERO));
            float lo, hi; unpack2(acc, lo, hi);
            a[s] = lo + hi;
        }

        // ---- select-free reduce-scatter over the 4 dg-lanes ----
        float b[8];
#pragma unroll
        for (int i = 0; i < 4; i++) {
#pragma unroll
            for (int c0 = 0; c0 < 2; c0++) {
                b[2*i + c0] = a[4*i + (c0 ^ 2)]
                            + __shfl_xor_sync(FULLMASK, a[4*i + c0], 2);
            }
        }
        float sdot[4];
#pragma unroll
        for (int i = 0; i < 4; i++) {
            sdot[i] = b[2*i + 1] + __shfl_xor_sync(FULLMASK, b[2*i + 0], 1);
        }
        // sdot[i] = <z[m], u> for m = 4*i + (dg^3).

        // ---- softmax over k (8 lanes, stride 4). |s|<=1 (unit vectors):
        //      shift-invariant softmax needs no max subtraction. ----
        float e[4], t[4];
#pragma unroll
        for (int i = 0; i < 4; i++) { e[i] = __expf(sdot[i]); t[i] = e[i]; }
#pragma unroll
        for (int i = 0; i < 4; i++) t[i] += __shfl_xor_sync(FULLMASK, t[i], 4);
#pragma unroll
        for (int i = 0; i < 4; i++) t[i] += __shfl_xor_sync(FULLMASK, t[i], 8);
#pragma unroll
        for (int i = 0; i < 4; i++) t[i] += __shfl_xor_sync(FULLMASK, t[i], 16);
        float pA[4];
#pragma unroll
        for (int i = 0; i < 4; i++) pA[i] = __fdividef(e[i], t[i]);
        // pA[i] ↔ m-offset dg^3.

        // ---- select-free allgather of p over the dg-group ----
        float pB[4], pC[4], pD[4];
#pragma unroll
        for (int i = 0; i < 4; i++) pB[i] = __shfl_xor_sync(FULLMASK, pA[i], 2); // dg^1
#pragma unroll
        for (int i = 0; i < 4; i++) pC[i] = __shfl_xor_sync(FULLMASK, pA[i], 1); // dg^2
#pragma unroll
        for (int i = 0; i < 4; i++) pD[i] = __shfl_xor_sync(FULLMASK, pB[i], 1); // dg

        // ---- phase B: unew = xn + sum_m p[m] * z[m] (packed) ----
        unew = xn;
#pragma unroll
        for (int i = 0; i < 4; i++) {
            unsigned long long w0 = pack2(pD[i], pD[i]);   // slot c=0 ↔ m-off dg
            unew.x = fma2(z[4*i + 0].x, w0, unew.x);
            unew.y = fma2(z[4*i + 0].y, w0, unew.y);
            unsigned long long w1 = pack2(pB[i], pB[i]);   // slot c=1 ↔ dg^1
            unew.x = fma2(z[4*i + 1].x, w1, unew.x);
            unew.y = fma2(z[4*i + 1].y, w1, unew.y);
            unsigned long long w2 = pack2(pC[i], pC[i]);   // slot c=2 ↔ dg^2
            unew.x = fma2(z[4*i + 2].x, w2, unew.x);
            unew.y = fma2(z[4*i + 2].y, w2, unew.y);
            unsigned long long w3 = pack2(pA[i], pA[i]);   // slot c=3 ↔ dg^3
            unew.x = fma2(z[4*i + 3].x, w3, unew.x);
            unew.y = fma2(z[4*i + 3].y, w3, unew.y);
        }

        if (it < ROUTIT - 1) {
            // per-capsule renormalize: ||unew||^2 over the 4 dg-lanes
            unsigned long long sq = fma2(unew.x, unew.x, fma2(unew.y, unew.y, ZERO));
            float lo, hi; unpack2(sq, lo, hi);
            float nsq = lo + hi;
            nsq += __shfl_xor_sync(FULLMASK, nsq, 1);
            nsq += __shfl_xor_sync(FULLMASK, nsq, 2);
            float inv = rsqrtf(fmaxf(nsq, 1e-24f));
            unsigned long long invp = pack2(inv, inv);
            u.x = mul2(unew.x, invp);
            u.y = mul2(unew.y, invp);
        }
    }

    // relu + store
    float f0, f1, f2, f3;
    unpack2(unew.x, f0, f1);
    unpack2(unew.y, f2, f3);
    float4 o;
    o.x = fmaxf(f0, 0.f); o.y = fmaxf(f1, 0.f);
    o.z = fmaxf(f2, 0.f); o.w = fmaxf(f3, 0.f);
    reinterpret_cast<float4*>(out)[node * 32 + lane] = o;
}

__global__ __launch_bounds__(256) void routing1_kernel(const int* __restrict__ nb)
{
    routing_warp(g_xn, nb, g_h1);
}

__global__ __launch_bounds__(256) void routing2_kernel(const int* __restrict__ nb,
                                                       float* __restrict__ out)
{
    routing_warp(g_y, nb, out);
}

// ---------------------------------------------------------------------------
// K3: y = normalize_per_capsule( relu( h1 @ W^T + b ) )  -> g_y
// Block: 32 nodes x 128 cols. 256 threads, each computes 4 nodes x 4 cols.
// ---------------------------------------------------------------------------
__global__ __launch_bounds__(256) void fc_kernel(const float* __restrict__ W,
                                                 const float* __restrict__ bias)
{
    __shared__ __align__(16) float Hs[32 * 36];     // Hs[node*36 + kk]
    __shared__ __align__(16) float Ws[32 * 132];    // Ws[kk*132 + j]  (transposed)

    const int t    = threadIdx.x;
    const int row0 = blockIdx.x * 32;
    const int ng   = t >> 5;        // warp id = node group (4 nodes)
    const int cg   = t & 31;        // col group (4 cols)
    const int c0   = cg * 4;

    float acc[4][4];
#pragma unroll
    for (int i = 0; i < 4; i++)
#pragma unroll
        for (int j = 0; j < 4; j++) acc[i][j] = 0.f;

    float bv[4];
#pragma unroll
    for (int j = 0; j < 4; j++) bv[j] = bias[c0 + j];

    const int lr = t >> 3;          // 0..31
    const int lc = t & 7;           // 0..7

    for (int kt = 0; kt < 4; kt++) {
        {
            int gr = row0 + lr;
            float4 hv = make_float4(0.f, 0.f, 0.f, 0.f);
            if (gr < N_NODES)
                hv = *reinterpret_cast<const float4*>(g_h1 + gr * DIM + kt * 32 + lc * 4);
            *reinterpret_cast<float4*>(Hs + lr * 36 + lc * 4) = hv;
        }
#pragma unroll
        for (int r = 0; r < 4; r++) {
            int j = lr + 32 * r;
            float4 wv = *reinterpret_cast<const float4*>(W + j * DIM + kt * 32 + lc * 4);
            Ws[(lc * 4 + 0) * 132 + j] = wv.x;
            Ws[(lc * 4 + 1) * 132 + j] = wv.y;
            Ws[(lc * 4 + 2) * 132 + j] = wv.z;
            Ws[(lc * 4 + 3) * 132 + j] = wv.w;
        }
        __syncthreads();

#pragma unroll
        for (int kk = 0; kk < 32; kk++) {
            float4 wq = *reinterpret_cast<const float4*>(Ws + kk * 132 + c0);
            float h0  = Hs[(ng * 4 + 0) * 36 + kk];
            float h1v = Hs[(ng * 4 + 1) * 36 + kk];
            float h2  = Hs[(ng * 4 + 2) * 36 + kk];
            float h3  = Hs[(ng * 4 + 3) * 36 + kk];
            acc[0][0] += h0 * wq.x; acc[0][1] += h0 * wq.y; acc[0][2] += h0 * wq.z; acc[0][3] += h0 * wq.w;
            acc[1][0] += h1v * wq.x; acc[1][1] += h1v * wq.y; acc[1][2] += h1v * wq.z; acc[1][3] += h1v * wq.w;
            acc[2][0] += h2 * wq.x; acc[2][1] += h2 * wq.y; acc[2][2] += h2 * wq.z; acc[2][3] += h2 * wq.w;
            acc[3][0] += h3 * wq.x; acc[3][1] += h3 * wq.y; acc[3][2] += h3 * wq.z; acc[3][3] += h3 * wq.w;
        }
        __syncthreads();
    }

#pragma unroll
    for (int i = 0; i < 4; i++) {
        float v0 = fmaxf(acc[i][0] + bv[0], 0.f);
        float v1 = fmaxf(acc[i][1] + bv[1], 0.f);
        float v2 = fmaxf(acc[i][2] + bv[2], 0.f);
        float v3 = fmaxf(acc[i][3] + bv[3], 0.f);
        float ss = v0*v0 + v1*v1 + v2*v2 + v3*v3;
        ss += __shfl_xor_sync(FULLMASK, ss, 1);
        ss += __shfl_xor_sync(FULLMASK, ss, 2);
        float inv = rsqrtf(fmaxf(ss, 1e-24f));
        int gr = row0 + ng * 4 + i;
        if (gr < N_NODES) {
            *reinterpret_cast<float4*>(g_y + gr * DIM + c0) =
                make_float4(v0 * inv, v1 * inv, v2 * inv, v3 * inv);
        }
    }
}

// ---------------------------------------------------------------------------
extern "C" void kernel_launch(void* const* d_in, const int* in_sizes, int n_in,
                              void* d_out, int out_size)
{
    const float* x  = (const float*)d_in[0];
    const int*   nb = (const int*)  d_in[1];
    const float* w  = (const float*)d_in[2];
    const float* b  = (const float*)d_in[3];
    float* out = (float*)d_out;

    (void)in_sizes; (void)n_in; (void)out_size;

    int ncaps_total = N_NODES * NCAPS;
    normalize_kernel<<<(ncaps_total + 255) / 256, 256>>>(x);
    routing1_kernel<<<N_NODES / 8, 256>>>(nb);        // 50000 = 6250 * 8
    fc_kernel<<<(N_NODES + 31) / 32, 256>>>(w, b);
    routing2_kernel<<<N_NODES / 8, 256>>>(nb, out);
}

// round 5
// speedup vs baseline: 1.0793x; 1.0793x over previous
#include <cuda_runtime.h>

#define N_NODES 50000
#define M_NB    16
#define NCAPS   8
#define NHID    16
#define DIM     128
#define ROUTIT  6

#define FULLMASK 0xffffffffu

// Scratch (no allocation allowed): static device buffers.
__device__ float g_xn[N_NODES * DIM];  // normalized layer-0 input
__device__ float g_h1[N_NODES * DIM];  // layer-0 routing output (relu'd)
__device__ float g_y [N_NODES * DIM];  // normalize(relu(fc(h1)))

// ---- f32x2 packed helpers (sm_103a) ---------------------------------------
__device__ __forceinline__ unsigned long long fma2(unsigned long long a,
                                                   unsigned long long b,
                                                   unsigned long long c)
{
    unsigned long long d;
    asm("fma.rn.f32x2 %0, %1, %2, %3;" : "=l"(d) : "l"(a), "l"(b), "l"(c));
    return d;
}
__device__ __forceinline__ unsigned long long add2(unsigned long long a,
                                                   unsigned long long b)
{
    unsigned long long d;
    asm("add.rn.f32x2 %0, %1, %2;" : "=l"(d) : "l"(a), "l"(b));
    return d;
}
__device__ __forceinline__ unsigned long long mul2(unsigned long long a,
                                                   unsigned long long b)
{
    unsigned long long d;
    asm("mul.rn.f32x2 %0, %1, %2;" : "=l"(d) : "l"(a), "l"(b));
    return d;
}
__device__ __forceinline__ unsigned long long pack2(float lo, float hi)
{
    unsigned long long d;
    asm("mov.b64 %0, {%1, %2};" : "=l"(d) : "f"(lo), "f"(hi));
    return d;
}
__device__ __forceinline__ void unpack2(unsigned long long v, float& lo, float& hi)
{
    asm("mov.b64 {%0, %1}, %2;" : "=f"(lo), "=f"(hi) : "l"(v));
}

// ---------------------------------------------------------------------------
// K1: per-capsule L2 normalize of raw x -> g_xn
// ---------------------------------------------------------------------------
__global__ __launch_bounds__(256) void normalize_kernel(const float* __restrict__ x)
{
    int idx = blockIdx.x * blockDim.x + threadIdx.x;       // capsule index
    if (idx >= N_NODES * NCAPS) return;
    const float4* src = reinterpret_cast<const float4*>(x) + idx * 4;
    float4 v0 = src[0], v1 = src[1], v2 = src[2], v3 = src[3];
    float ss = v0.x*v0.x + v0.y*v0.y + v0.z*v0.z + v0.w*v0.w
             + v1.x*v1.x + v1.y*v1.y + v1.z*v1.z + v1.w*v1.w
             + v2.x*v2.x + v2.y*v2.y + v2.z*v2.z + v2.w*v2.w
             + v3.x*v3.x + v3.y*v3.y + v3.z*v3.z + v3.w*v3.w;
    float inv = rsqrtf(fmaxf(ss, 1e-24f));
    float4* dst = reinterpret_cast<float4*>(g_xn) + idx * 4;
    v0.x*=inv; v0.y*=inv; v0.z*=inv; v0.w*=inv;
    v1.x*=inv; v1.y*=inv; v1.z*=inv; v1.w*=inv;
    v2.x*=inv; v2.y*=inv; v2.z*=inv; v2.w*=inv;
    v3.x*=inv; v3.y*=inv; v3.z*=inv; v3.w*=inv;
    dst[0]=v0; dst[1]=v1; dst[2]=v2; dst[3]=v3;
}

// ---------------------------------------------------------------------------
// Warp-per-node routing. Lane L: capsule k = L>>2, dim-group dg = L&3.
// Permuted gather: register slot s holds z of neighbor m = (s&~3)|((s&3)^dg)
// => butterfly reduce-scatter and p-allgather need NO runtime selects.
// After reduce-scatter, sdot[i] is the full dot for m = 4i + (dg^3).
// Allgather (depth 1): pB=xor2(pA) ↔ dg^1, pC=xor1(pA) ↔ dg^2,
// pD=xor3(pA) ↔ dg. Slot c=0/1/2/3 uses pD/pB/pC/pA (compile-time).
// ---------------------------------------------------------------------------
__device__ __forceinline__ void routing_warp(const float* __restrict__ src,
                                             const int*   __restrict__ nb,
                                             float*       __restrict__ out,
                                             int node)
{
    const int lane = threadIdx.x & 31;
    const int dg   = lane & 3;

    // Broadcast neighbor indices: lanes 0..15 load one each.
    int nbv = 0;
    if (lane < 16) nbv = nb[node * M_NB + lane];

    const ulonglong2* srcv = reinterpret_cast<const ulonglong2*>(src);

    // xn / u init: this lane's 4 floats as two f32x2 pairs.
    ulonglong2 xn = srcv[node * 32 + lane];
    ulonglong2 u  = xn;

    // Gather z with dg-permuted slots (coalesced 16B per lane per row).
    ulonglong2 z[M_NB];
#pragma unroll
    for (int s = 0; s < M_NB; s++) {
        int row = __shfl_sync(FULLMASK, nbv, s ^ dg);
        z[s] = srcv[row * 32 + lane];
    }

    const unsigned long long ZERO = 0;
    ulonglong2 unew = xn;

#pragma unroll
    for (int it = 0; it < ROUTIT; it++) {
        // ---- phase A: partial dots (own 4 dims) for each slot ----
        float a[M_NB];
#pragma unroll
        for (int s = 0; s < M_NB; s++) {
            unsigned long long acc = fma2(z[s].x, u.x, fma2(z[s].y, u.y, ZERO));
            float lo, hi; unpack2(acc, lo, hi);
            a[s] = lo + hi;
        }

        // ---- select-free reduce-scatter over the 4 dg-lanes ----
        float b[8];
#pragma unroll
        for (int i = 0; i < 4; i++) {
#pragma unroll
            for (int c0 = 0; c0 < 2; c0++) {
                b[2*i + c0] = a[4*i + (c0 ^ 2)]
                            + __shfl_xor_sync(FULLMASK, a[4*i + c0], 2);
            }
        }
        float sdot[4];
#pragma unroll
        for (int i = 0; i < 4; i++) {
            sdot[i] = b[2*i + 1] + __shfl_xor_sync(FULLMASK, b[2*i + 0], 1);
        }
        // sdot[i] = <z[m], u> for m = 4*i + (dg^3).

        // ---- softmax over k (8 lanes, stride 4). |s|<=1 (unit vectors):
        //      shift-invariant softmax needs no max subtraction. ----
        float e[4], t[4];
#pragma unroll
        for (int i = 0; i < 4; i++) { e[i] = __expf(sdot[i]); t[i] = e[i]; }
#pragma unroll
        for (int i = 0; i < 4; i++) t[i] += __shfl_xor_sync(FULLMASK, t[i], 4);
#pragma unroll
        for (int i = 0; i < 4; i++) t[i] += __shfl_xor_sync(FULLMASK, t[i], 8);
#pragma unroll
        for (int i = 0; i < 4; i++) t[i] += __shfl_xor_sync(FULLMASK, t[i], 16);
        float pA[4];
#pragma unroll
        for (int i = 0; i < 4; i++) pA[i] = __fdividef(e[i], t[i]);
        // pA[i] ↔ m-offset dg^3.

        // ---- depth-1 allgather of p over the dg-group ----
        float pB[4], pC[4], pD[4];
#pragma unroll
        for (int i = 0; i < 4; i++) pB[i] = __shfl_xor_sync(FULLMASK, pA[i], 2); // dg^1
#pragma unroll
        for (int i = 0; i < 4; i++) pC[i] = __shfl_xor_sync(FULLMASK, pA[i], 1); // dg^2
#pragma unroll
        for (int i = 0; i < 4; i++) pD[i] = __shfl_xor_sync(FULLMASK, pA[i], 3); // dg

        // ---- phase B: unew = xn + sum_m p[m] * z[m] (packed, 2 chains) ----
        ulonglong2 accA = xn;
        ulonglong2 accB; accB.x = ZERO; accB.y = ZERO;
#pragma unroll
        for (int i = 0; i < 4; i++) {
            unsigned long long w0 = pack2(pD[i], pD[i]);   // slot c=0 ↔ m-off dg
            accA.x = fma2(z[4*i + 0].x, w0, accA.x);
            accA.y = fma2(z[4*i + 0].y, w0, accA.y);
            unsigned long long w1 = pack2(pB[i], pB[i]);   // slot c=1 ↔ dg^1
            accA.x = fma2(z[4*i + 1].x, w1, accA.x);
            accA.y = fma2(z[4*i + 1].y, w1, accA.y);
            unsigned long long w2 = pack2(pC[i], pC[i]);   // slot c=2 ↔ dg^2
            accB.x = fma2(z[4*i + 2].x, w2, accB.x);
            accB.y = fma2(z[4*i + 2].y, w2, accB.y);
            unsigned long long w3 = pack2(pA[i], pA[i]);   // slot c=3 ↔ dg^3
            accB.x = fma2(z[4*i + 3].x, w3, accB.x);
            accB.y = fma2(z[4*i + 3].y, w3, accB.y);
        }
        unew.x = add2(accA.x, accB.x);
        unew.y = add2(accA.y, accB.y);

        if (it < ROUTIT - 1) {
            // per-capsule renormalize: ||unew||^2 over the 4 dg-lanes
            unsigned long long sq = fma2(unew.x, unew.x, fma2(unew.y, unew.y, ZERO));
            float lo, hi; unpack2(sq, lo, hi);
            float nsq = lo + hi;
            nsq += __shfl_xor_sync(FULLMASK, nsq, 1);
            nsq += __shfl_xor_sync(FULLMASK, nsq, 2);
            float inv = rsqrtf(fmaxf(nsq, 1e-24f));
            unsigned long long invp = pack2(inv, inv);
            u.x = mul2(unew.x, invp);
            u.y = mul2(unew.y, invp);
        }
    }

    // relu + store
    float f0, f1, f2, f3;
    unpack2(unew.x, f0, f1);
    unpack2(unew.y, f2, f3);
    float4 o;
    o.x = fmaxf(f0, 0.f); o.y = fmaxf(f1, 0.f);
    o.z = fmaxf(f2, 0.f); o.w = fmaxf(f3, 0.f);
    reinterpret_cast<float4*>(out)[node * 32 + lane] = o;
}

__global__ __launch_bounds__(128, 5) void routing1_kernel(const int* __restrict__ nb)
{
    routing_warp(g_xn, nb, g_h1, blockIdx.x * 4 + (threadIdx.x >> 5));
}

__global__ __launch_bounds__(128, 5) void routing2_kernel(const int* __restrict__ nb,
                                                          float* __restrict__ out)
{
    routing_warp(g_y, nb, out, blockIdx.x * 4 + (threadIdx.x >> 5));
}

// ---------------------------------------------------------------------------
// K3: y = normalize_per_capsule( relu( h1 @ W^T + b ) )  -> g_y
// Block: 32 nodes x 128 cols. 256 threads, each computes 4 nodes x 4 cols.
// ---------------------------------------------------------------------------
__global__ __launch_bounds__(256) void fc_kernel(const float* __restrict__ W,
                                                 const float* __restrict__ bias)
{
    __shared__ __align__(16) float Hs[32 * 36];     // Hs[node*36 + kk]
    __shared__ __align__(16) float Ws[32 * 132];    // Ws[kk*132 + j]  (transposed)

    const int t    = threadIdx.x;
    const int row0 = blockIdx.x * 32;
    const int ng   = t >> 5;        // warp id = node group (4 nodes)
    const int cg   = t & 31;        // col group (4 cols)
    const int c0   = cg * 4;

    float acc[4][4];
#pragma unroll
    for (int i = 0; i < 4; i++)
#pragma unroll
        for (int j = 0; j < 4; j++) acc[i][j] = 0.f;

    float bv[4];
#pragma unroll
    for (int j = 0; j < 4; j++) bv[j] = bias[c0 + j];

    const int lr = t >> 3;          // 0..31
    const int lc = t & 7;           // 0..7

    for (int kt = 0; kt < 4; kt++) {
        {
            int gr = row0 + lr;
            float4 hv = make_float4(0.f, 0.f, 0.f, 0.f);
            if (gr < N_NODES)
                hv = *reinterpret_cast<const float4*>(g_h1 + gr * DIM + kt * 32 + lc * 4);
            *reinterpret_cast<float4*>(Hs + lr * 36 + lc * 4) = hv;
        }
#pragma unroll
        for (int r = 0; r < 4; r++) {
            int j = lr + 32 * r;
            float4 wv = *reinterpret_cast<const float4*>(W + j * DIM + kt * 32 + lc * 4);
            Ws[(lc * 4 + 0) * 132 + j] = wv.x;
            Ws[(lc * 4 + 1) * 132 + j] = wv.y;
            Ws[(lc * 4 + 2) * 132 + j] = wv.z;
            Ws[(lc * 4 + 3) * 132 + j] = wv.w;
        }
        __syncthreads();

#pragma unroll
        for (int kk = 0; kk < 32; kk++) {
            float4 wq = *reinterpret_cast<const float4*>(Ws + kk * 132 + c0);
            float h0  = Hs[(ng * 4 + 0) * 36 + kk];
            float h1v = Hs[(ng * 4 + 1) * 36 + kk];
            float h2  = Hs[(ng * 4 + 2) * 36 + kk];
            float h3  = Hs[(ng * 4 + 3) * 36 + kk];
            acc[0][0] += h0 * wq.x; acc[0][1] += h0 * wq.y; acc[0][2] += h0 * wq.z; acc[0][3] += h0 * wq.w;
            acc[1][0] += h1v * wq.x; acc[1][1] += h1v * wq.y; acc[1][2] += h1v * wq.z; acc[1][3] += h1v * wq.w;
            acc[2][0] += h2 * wq.x; acc[2][1] += h2 * wq.y; acc[2][2] += h2 * wq.z; acc[2][3] += h2 * wq.w;
            acc[3][0] += h3 * wq.x; acc[3][1] += h3 * wq.y; acc[3][2] += h3 * wq.z; acc[3][3] += h3 * wq.w;
        }
        __syncthreads();
    }

#pragma unroll
    for (int i = 0; i < 4; i++) {
        float v0 = fmaxf(acc[i][0] + bv[0], 0.f);
        float v1 = fmaxf(acc[i][1] + bv[1], 0.f);
        float v2 = fmaxf(acc[i][2] + bv[2], 0.f);
        float v3 = fmaxf(acc[i][3] + bv[3], 0.f);
        float ss = v0*v0 + v1*v1 + v2*v2 + v3*v3;
        ss += __shfl_xor_sync(FULLMASK, ss, 1);
        ss += __shfl_xor_sync(FULLMASK, ss, 2);
        float inv = rsqrtf(fmaxf(ss, 1e-24f));
        int gr = row0 + ng * 4 + i;
        if (gr < N_NODES) {
            *reinterpret_cast<float4*>(g_y + gr * DIM + c0) =
                make_float4(v0 * inv, v1 * inv, v2 * inv, v3 * inv);
        }
    }
}

// ---------------------------------------------------------------------------
extern "C" void kernel_launch(void* const* d_in, const int* in_sizes, int n_in,
                              void* d_out, int out_size)
{
    const float* x  = (const float*)d_in[0];
    const int*   nb = (const int*)  d_in[1];
    const float* w  = (const float*)d_in[2];
    const float* b  = (const float*)d_in[3];
    float* out = (float*)d_out;

    (void)in_sizes; (void)n_in; (void)out_size;

    int ncaps_total = N_NODES * NCAPS;
    normalize_kernel<<<(ncaps_total + 255) / 256, 256>>>(x);
    routing1_kernel<<<N_NODES / 4, 128>>>(nb);        // 50000 = 12500 * 4
    fc_kernel<<<(N_NODES + 31) / 32, 256>>>(w, b);
    routing2_kernel<<<N_NODES / 4, 128>>>(nb, out);
}